// round 16
// baseline (speedup 1.0000x reference)
#include <cuda_runtime.h>
#include <math.h>
#include <stdint.h>

#define NL 12
#define NH 12
#define NC 768
#define NV 50257
#define NVP 50304
#define NT 1024
#define NB 4
#define ND 64
#define NTOK (NB * NT)

// ---- scratch ----
__device__ float g_x[NTOK * NC];
__device__ float g_h[NTOK * NC];
__device__ float g_qkv[NTOK * 3 * NC];
__device__ float g_y[NTOK * NC];
__device__ float g_fc[NTOK * 4 * NC];
__device__ float g_lmT[NC * NVP];

// =====================================================================
// helpers
// =====================================================================
__device__ __forceinline__ uint32_t smem_u32(const void* p) {
    uint32_t a;
    asm("{ .reg .u64 t; cvta.to.shared.u64 t, %1; cvt.u32.u64 %0, t; }"
        : "=r"(a) : "l"(p));
    return a;
}
__device__ __forceinline__ void cpa16(uint32_t dst, const void* src) {
    asm volatile("cp.async.cg.shared.global [%0], [%1], 16;"
                 :: "r"(dst), "l"(src));
}
__device__ __forceinline__ float gelu_f(float u) {
    return 0.5f * u * (1.0f + tanhf(0.7978845608028654f * (u + 0.044715f * u * u * u)));
}

// ---- packed f32x2 ----
__device__ __forceinline__ unsigned long long pack2(float x, float y) {
    unsigned long long r;
    asm("mov.b64 %0, {%1, %2};" : "=l"(r) : "f"(x), "f"(y));
    return r;
}
__device__ __forceinline__ void fma2(unsigned long long& c,
                                     unsigned long long a, unsigned long long b) {
    asm("fma.rn.f32x2 %0, %1, %2, %0;" : "+l"(c) : "l"(a), "l"(b));
}
__device__ __forceinline__ void mul2(unsigned long long& d,
                                     unsigned long long a, unsigned long long b) {
    asm("mul.rn.f32x2 %0, %1, %2;" : "=l"(d) : "l"(a), "l"(b));
}
__device__ __forceinline__ void unpack2(unsigned long long v, float& x, float& y) {
    asm("mov.b64 {%0, %1}, %2;" : "=f"(x), "=f"(y) : "l"(v));
}

// =====================================================================
// lm_head transpose: [NV][NC] -> [NC][NVP]
// =====================================================================
__global__ void transpose_lm(const float* __restrict__ src, float* __restrict__ dst) {
    __shared__ float t[32][33];
    int v0 = blockIdx.x * 32, c0 = blockIdx.y * 32;
    int tx = threadIdx.x, ty = threadIdx.y;
    #pragma unroll
    for (int i = ty; i < 32; i += 8)
        t[i][tx] = (v0 + i < NV) ? src[(size_t)(v0 + i) * NC + c0 + tx] : 0.f;
    __syncthreads();
    #pragma unroll
    for (int i = ty; i < 32; i += 8)
        dst[(size_t)(c0 + i) * NVP + v0 + tx] = t[tx][i];
}

// =====================================================================
// embedding
// =====================================================================
__global__ void embed_kernel(const int* __restrict__ idx,
                             const float* __restrict__ wte,
                             const float* __restrict__ wpe,
                             float* __restrict__ x) {
    int row = blockIdx.x;
    int t = row % NT;
    int tok = idx[row];
    const float* we = wte + (size_t)tok * NC;
    const float* wp = wpe + (size_t)t * NC;
    float* out = x + (size_t)row * NC;
    for (int c = threadIdx.x; c < NC; c += blockDim.x)
        out[c] = we[c] + wp[c];
}

// =====================================================================
// layernorm
// =====================================================================
__global__ void ln_kernel(const float* __restrict__ x,
                          const float* __restrict__ w,
                          const float* __restrict__ b,
                          float* __restrict__ out) {
    int row = blockIdx.x;
    const float* xr = x + (size_t)row * NC;
    __shared__ float red[32];
    int tid = threadIdx.x;
    int nwarp = blockDim.x >> 5;

    float s = 0.f;
    for (int c = tid; c < NC; c += blockDim.x) s += xr[c];
    #pragma unroll
    for (int o = 16; o; o >>= 1) s += __shfl_xor_sync(0xffffffffu, s, o);
    if ((tid & 31) == 0) red[tid >> 5] = s;
    __syncthreads();
    if (tid < 32) {
        float v = (tid < nwarp) ? red[tid] : 0.f;
        #pragma unroll
        for (int o = 16; o; o >>= 1) v += __shfl_xor_sync(0xffffffffu, v, o);
        if (tid == 0) red[0] = v;
    }
    __syncthreads();
    float mu = red[0] * (1.0f / NC);
    __syncthreads();

    float s2 = 0.f;
    for (int c = tid; c < NC; c += blockDim.x) {
        float d = xr[c] - mu;
        s2 += d * d;
    }
    #pragma unroll
    for (int o = 16; o; o >>= 1) s2 += __shfl_xor_sync(0xffffffffu, s2, o);
    if ((tid & 31) == 0) red[tid >> 5] = s2;
    __syncthreads();
    if (tid < 32) {
        float v = (tid < nwarp) ? red[tid] : 0.f;
        #pragma unroll
        for (int o = 16; o; o >>= 1) v += __shfl_xor_sync(0xffffffffu, v, o);
        if (tid == 0) red[0] = v;
    }
    __syncthreads();
    float var = red[0] * (1.0f / NC);
    float rstd = rsqrtf(var + 1e-5f);
    float* outr = out + (size_t)row * NC;
    for (int c = tid; c < NC; c += blockDim.x)
        outr[c] = (xr[c] - mu) * rstd * w[c] + b[c];
}

// =====================================================================
// fp32 SGEMM (NN), FFMA2 with pre-packed smem operands (zero in-loop packs)
// A stored duplicated as 64-bit {a,a}; B pairs loaded via ld.shared.v2.b64.
// =====================================================================
#define BM 128
#define BN 128
#define BKS 16

__global__ void __launch_bounds__(256, 2) sgemm_nn(
    const float* __restrict__ A, const float* __restrict__ W,
    const float* __restrict__ bias, const float* __restrict__ res,
    float* __restrict__ C, int M, int N, int ldb, int K, int act)
{
    __shared__ unsigned long long AsD[2][BKS][BM];   // 32 KB: {a,a} per row
    __shared__ float Bs[2][BKS][BN];                 // 16 KB

    int tid = threadIdx.x;
    int lane = tid & 31, warp = tid >> 5;
    int wm = (warp & 3) * 32, wn = (warp >> 2) * 64;
    int lm = lane & 3, ln = lane >> 2;
    int bm = blockIdx.x * BM, bn = blockIdx.y * BN;

    int arow = tid & 127, akq = (tid >> 7) * 8;
    float4 apre0, apre1;

    unsigned long long c2[8][4];
    #pragma unroll
    for (int i = 0; i < 8; i++)
        #pragma unroll
        for (int j = 0; j < 4; j++) c2[i][j] = 0ULL;

    const int S = K / BKS;

    {
        const float* ap = A + (size_t)(bm + arow) * K + akq;
        apre0 = *(const float4*)(ap);
        apre1 = *(const float4*)(ap + 4);
        #pragma unroll
        for (int i = 0; i < 2; i++) {
            int id = tid + i * 256;
            int k = id >> 5, n16 = (id & 31) * 4;
            cpa16(smem_u32(&Bs[0][k][n16]), W + (size_t)k * ldb + bn + n16);
        }
        asm volatile("cp.async.commit_group;");
        #pragma unroll
        for (int i = 0; i < 4; i++) {
            float v = ((float*)&apre0)[i];
            AsD[0][akq + i][arow] = pack2(v, v);
        }
        #pragma unroll
        for (int i = 0; i < 4; i++) {
            float v = ((float*)&apre1)[i];
            AsD[0][akq + 4 + i][arow] = pack2(v, v);
        }
        asm volatile("cp.async.wait_group 0;");
        __syncthreads();
    }

    for (int s = 0; s < S; s++) {
        int cur = s & 1, nxt = cur ^ 1;
        bool more = (s + 1 < S);
        if (more) {
            const float* ap = A + (size_t)(bm + arow) * K + (s + 1) * BKS + akq;
            apre0 = *(const float4*)(ap);
            apre1 = *(const float4*)(ap + 4);
            #pragma unroll
            for (int i = 0; i < 2; i++) {
                int id = tid + i * 256;
                int k = id >> 5, n16 = (id & 31) * 4;
                cpa16(smem_u32(&Bs[nxt][k][n16]),
                      W + (size_t)((s + 1) * BKS + k) * ldb + bn + n16);
            }
            asm volatile("cp.async.commit_group;");
        }

        #pragma unroll
        for (int k = 0; k < BKS; k++) {
            ulonglong2 a01 = *(const ulonglong2*)&AsD[cur][k][wm + lm * 4];
            ulonglong2 a23 = *(const ulonglong2*)&AsD[cur][k][wm + lm * 4 + 2];
            ulonglong2 a45 = *(const ulonglong2*)&AsD[cur][k][wm + lm * 4 + 16];
            ulonglong2 a67 = *(const ulonglong2*)&AsD[cur][k][wm + lm * 4 + 18];
            ulonglong2 bA = *(const ulonglong2*)&Bs[cur][k][wn + ln * 4];
            ulonglong2 bB = *(const ulonglong2*)&Bs[cur][k][wn + ln * 4 + 32];
            unsigned long long a2[8] = {a01.x, a01.y, a23.x, a23.y,
                                        a45.x, a45.y, a67.x, a67.y};
            unsigned long long b2[4] = {bA.x, bA.y, bB.x, bB.y};
            #pragma unroll
            for (int i = 0; i < 8; i++)
                #pragma unroll
                for (int j = 0; j < 4; j++)
                    fma2(c2[i][j], a2[i], b2[j]);
        }

        if (more) {
            #pragma unroll
            for (int i = 0; i < 4; i++) {
                float v = ((float*)&apre0)[i];
                AsD[nxt][akq + i][arow] = pack2(v, v);
            }
            #pragma unroll
            for (int i = 0; i < 4; i++) {
                float v = ((float*)&apre1)[i];
                AsD[nxt][akq + 4 + i][arow] = pack2(v, v);
            }
            asm volatile("cp.async.wait_group 0;");
        }
        __syncthreads();
    }

    // ---- epilogue ----
    bool vec_ok = ((N & 3) == 0);
    #pragma unroll
    for (int i = 0; i < 8; i++) {
        int m = bm + wm + (i >> 2) * 16 + lm * 4 + (i & 3);
        #pragma unroll
        for (int jq = 0; jq < 2; jq++) {
            int n0 = bn + wn + jq * 32 + ln * 4;
            float cv[4];
            unpack2(c2[i][jq * 2 + 0], cv[0], cv[1]);
            unpack2(c2[i][jq * 2 + 1], cv[2], cv[3]);
            float4 v;
            float* vp = (float*)&v;
            #pragma unroll
            for (int j = 0; j < 4; j++) {
                float u = cv[j];
                int col = n0 + j;
                if (bias) u += bias[col];
                if (act) u = gelu_f(u);
                if (res && col < N) u += res[(size_t)m * N + col];
                vp[j] = u;
            }
            if (vec_ok && n0 + 3 < N) {
                *(float4*)&C[(size_t)m * N + n0] = v;
            } else {
                #pragma unroll
                for (int j = 0; j < 4; j++)
                    if (n0 + j < N) C[(size_t)m * N + n0 + j] = vp[j];
            }
        }
    }
}

// =====================================================================
// FLASH ATTENTION (fp32, FFMA2 with pre-packed Q and v2.b64 K/V loads)
// =====================================================================
#define FBQ 64
#define FPITCH 68
#define QP 68   // ull pitch for duplicated Q
// QtD: 64*68*8 = 34816 ; Kt/Vs/Ss: 3 * 64*68*4 = 52224 ; stats 768
#define FSMEM_BYTES (34816 + 52224 + 768)

__global__ void __launch_bounds__(256) flash_attn(
    const float* __restrict__ qkv, float* __restrict__ y)
{
    extern __shared__ char fsm[];
    unsigned long long* QtD = (unsigned long long*)fsm;          // [d][q] {q,q}
    float* Kt = (float*)(fsm + 34816);                           // [d][k]
    float* Vs = Kt + 64 * FPITCH;                                // [k][d]
    float* Ss = Vs + 64 * FPITCH;                                // [q][k]
    float* sm_m = Ss + 64 * FPITCH;
    float* sm_l = sm_m + 64;
    float* sm_a = sm_l + 64;

    int qt = blockIdx.x, h = blockIdx.y, b = blockIdx.z;
    int tid = threadIdx.x, lane = tid & 31, warp = tid >> 5;
    int q0 = qt * FBQ;
    const size_t rs = 3 * NC;
    const float* qbase = qkv + ((size_t)b * NT) * rs + h * ND;
    const float* kbase = qkv + ((size_t)b * NT) * rs + NC + h * ND;
    const float* vbase = qkv + ((size_t)b * NT) * rs + 2 * NC + h * ND;

    unsigned long long O2[8];
    #pragma unroll
    for (int i = 0; i < 8; i++) O2[i] = 0ULL;
    if (tid < 64) { sm_m[tid] = -1e30f; sm_l[tid] = 0.f; }

    // Q tile -> QtD[d][q] duplicated
    #pragma unroll
    for (int i = 0; i < 4; i++) {
        int idx = tid + i * 256;
        int q = idx & 63, c4 = (idx >> 6) * 4;
        float4 v = *(const float4*)(qbase + (size_t)(q0 + q) * rs + c4);
        QtD[(c4 + 0) * QP + q] = pack2(v.x, v.x);
        QtD[(c4 + 1) * QP + q] = pack2(v.y, v.y);
        QtD[(c4 + 2) * QP + q] = pack2(v.z, v.z);
        QtD[(c4 + 3) * QP + q] = pack2(v.w, v.w);
    }
    __syncthreads();

    int tq = (tid & 15) * 4, tk = (tid >> 4) * 4;
    int pvq = warp * 8 + (lane & 7), dg = lane >> 3;

    for (int kt = 0; kt <= qt; kt++) {
        int kb = kt * FBQ;

        #pragma unroll
        for (int i = 0; i < 4; i++) {
            int idx = tid + i * 256;
            int k = idx & 63, c4 = (idx >> 6) * 4;
            float4 v = *(const float4*)(kbase + (size_t)(kb + k) * rs + c4);
            Kt[(c4 + 0) * FPITCH + k] = v.x;
            Kt[(c4 + 1) * FPITCH + k] = v.y;
            Kt[(c4 + 2) * FPITCH + k] = v.z;
            Kt[(c4 + 3) * FPITCH + k] = v.w;
            float4 w = *(const float4*)(vbase + (size_t)(kb + k) * rs + c4);
            *(float4*)&Vs[k * FPITCH + c4] = w;
        }
        __syncthreads();

        // scores: 3 LDS.128 + 8 FFMA2 per d, no packs
        unsigned long long s2[4][2];
        #pragma unroll
        for (int i = 0; i < 4; i++) { s2[i][0] = 0ULL; s2[i][1] = 0ULL; }
        #pragma unroll 8
        for (int d = 0; d < 64; d++) {
            ulonglong2 q01 = *(const ulonglong2*)&QtD[d * QP + tq];
            ulonglong2 q23 = *(const ulonglong2*)&QtD[d * QP + tq + 2];
            ulonglong2 kk = *(const ulonglong2*)&Kt[d * FPITCH + tk];
            fma2(s2[0][0], q01.x, kk.x); fma2(s2[0][1], q01.x, kk.y);
            fma2(s2[1][0], q01.y, kk.x); fma2(s2[1][1], q01.y, kk.y);
            fma2(s2[2][0], q23.x, kk.x); fma2(s2[2][1], q23.x, kk.y);
            fma2(s2[3][0], q23.y, kk.x); fma2(s2[3][1], q23.y, kk.y);
        }
        bool diag = (kt == qt);
        #pragma unroll
        for (int i = 0; i < 4; i++) {
            float sv[4];
            unpack2(s2[i][0], sv[0], sv[1]);
            unpack2(s2[i][1], sv[2], sv[3]);
            float4 v;
            float* vp = (float*)&v;
            #pragma unroll
            for (int j = 0; j < 4; j++) {
                float val = sv[j] * 0.125f;
                if (diag && (kb + tk + j) > (q0 + tq + i)) val = -1e30f;
                vp[j] = val;
            }
            *(float4*)&Ss[(tq + i) * FPITCH + tk] = v;
        }
        __syncthreads();

        // online softmax
        for (int r = 0; r < 8; r++) {
            int q = warp * 8 + r;
            float s0 = Ss[q * FPITCH + lane];
            float s1 = Ss[q * FPITCH + lane + 32];
            float mx = fmaxf(s0, s1);
            #pragma unroll
            for (int o = 16; o; o >>= 1)
                mx = fmaxf(mx, __shfl_xor_sync(0xffffffffu, mx, o));
            float mo = sm_m[q];
            float mn = fmaxf(mo, mx);
            float p0 = __expf(s0 - mn), p1 = __expf(s1 - mn);
            float ps = p0 + p1;
            #pragma unroll
            for (int o = 16; o; o >>= 1)
                ps += __shfl_xor_sync(0xffffffffu, ps, o);
            Ss[q * FPITCH + lane] = p0;
            Ss[q * FPITCH + lane + 32] = p1;
            if (lane == 0) {
                float al = __expf(mo - mn);
                sm_a[q] = al;
                sm_l[q] = sm_l[q] * al + ps;
                sm_m[q] = mn;
            }
        }
        __syncthreads();

        // PV accumulate: ulonglong2 loads of V pairs
        {
            float al = sm_a[pvq];
            unsigned long long al2 = pack2(al, al);
            #pragma unroll
            for (int i = 0; i < 8; i++) mul2(O2[i], O2[i], al2);
        }
        #pragma unroll 4
        for (int k = 0; k < 64; k++) {
            float p = Ss[pvq * FPITCH + k];
            unsigned long long p2 = pack2(p, p);
            const ulonglong2* vr = (const ulonglong2*)&Vs[k * FPITCH + dg * 16];
            ulonglong2 v0 = vr[0], v1 = vr[1], v2v = vr[2], v3 = vr[3];
            fma2(O2[0], p2, v0.x); fma2(O2[1], p2, v0.y);
            fma2(O2[2], p2, v1.x); fma2(O2[3], p2, v1.y);
            fma2(O2[4], p2, v2v.x); fma2(O2[5], p2, v2v.y);
            fma2(O2[6], p2, v3.x); fma2(O2[7], p2, v3.y);
        }
        __syncthreads();
    }

    float inv = 1.0f / sm_l[pvq];
    float* yo = y + ((size_t)(b * NT + q0 + pvq)) * NC + h * ND + dg * 16;
    #pragma unroll
    for (int j = 0; j < 4; j++) {
        float x0, x1, x2, x3;
        unpack2(O2[j * 2 + 0], x0, x1);
        unpack2(O2[j * 2 + 1], x2, x3);
        float4 v = make_float4(x0 * inv, x1 * inv, x2 * inv, x3 * inv);
        *(float4*)(yo + j * 4) = v;
    }
}

// =====================================================================
// launch
// =====================================================================
extern "C" void kernel_launch(void* const* d_in, const int* in_sizes, int n_in,
                              void* d_out, int out_size) {
    const int*   idx    = (const int*)d_in[0];
    const float* wte    = (const float*)d_in[1];
    const float* wpe    = (const float*)d_in[2];
    const float* ln1_w  = (const float*)d_in[3];
    const float* ln1_b  = (const float*)d_in[4];
    const float* ln2_w  = (const float*)d_in[5];
    const float* ln2_b  = (const float*)d_in[6];
    const float* attn_w = (const float*)d_in[7];
    const float* attn_b = (const float*)d_in[8];
    const float* proj_w = (const float*)d_in[9];
    const float* proj_b = (const float*)d_in[10];
    const float* fc_w   = (const float*)d_in[11];
    const float* fc_b   = (const float*)d_in[12];
    const float* fcp_w  = (const float*)d_in[13];
    const float* fcp_b  = (const float*)d_in[14];
    const float* lnf_w  = (const float*)d_in[15];
    const float* lnf_b  = (const float*)d_in[16];
    const float* lmh    = (const float*)d_in[17];
    float* out = (float*)d_out;

    float *x, *h, *qkv, *y, *fc, *lmT;
    cudaGetSymbolAddress((void**)&x, g_x);
    cudaGetSymbolAddress((void**)&h, g_h);
    cudaGetSymbolAddress((void**)&qkv, g_qkv);
    cudaGetSymbolAddress((void**)&y, g_y);
    cudaGetSymbolAddress((void**)&fc, g_fc);
    cudaGetSymbolAddress((void**)&lmT, g_lmT);

    cudaFuncSetAttribute(flash_attn, cudaFuncAttributeMaxDynamicSharedMemorySize,
                         FSMEM_BYTES);

    transpose_lm<<<dim3(NVP / 32, NC / 32), dim3(32, 8)>>>(lmh, lmT);
    embed_kernel<<<NTOK, 256>>>(idx, wte, wpe, x);

    for (int l = 0; l < NL; l++) {
        ln_kernel<<<NTOK, 256>>>(x, ln1_w + l * NC, ln1_b + l * NC, h);
        sgemm_nn<<<dim3(NTOK / BM, (3 * NC) / BN), 256>>>(
            h, attn_w + (size_t)l * NC * 3 * NC,
            attn_b + (size_t)l * 3 * NC, nullptr,
            qkv, NTOK, 3 * NC, 3 * NC, NC, 0);
        {
            dim3 grid(NT / FBQ, NH, NB);
            flash_attn<<<grid, 256, FSMEM_BYTES>>>(qkv, y);
        }
        sgemm_nn<<<dim3(NTOK / BM, NC / BN), 256>>>(
            y, proj_w + (size_t)l * NC * NC,
            proj_b + (size_t)l * NC, x,
            x, NTOK, NC, NC, NC, 0);
        ln_kernel<<<NTOK, 256>>>(x, ln2_w + l * NC, ln2_b + l * NC, h);
        sgemm_nn<<<dim3(NTOK / BM, (4 * NC) / BN), 256>>>(
            h, fc_w + (size_t)l * NC * 4 * NC,
            fc_b + (size_t)l * 4 * NC, nullptr,
            fc, NTOK, 4 * NC, 4 * NC, NC, 1);
        sgemm_nn<<<dim3(NTOK / BM, NC / BN), 256>>>(
            fc, fcp_w + (size_t)l * 4 * NC * NC,
            fcp_b + (size_t)l * NC, x,
            x, NTOK, NC, NC, 4 * NC, 0);
    }

    ln_kernel<<<NTOK, 256>>>(x, lnf_w, lnf_b, h);

    sgemm_nn<<<dim3(NTOK / BM, NVP / BN), 256>>>(
        h, lmT, nullptr, nullptr, out, NTOK, NV, NVP, NC, 0);
}

// round 17
// speedup vs baseline: 1.2150x; 1.2150x over previous
#include <cuda_runtime.h>
#include <math.h>
#include <stdint.h>

#define NL 12
#define NH 12
#define NC 768
#define NV 50257
#define NVP 50304
#define NT 1024
#define NB 4
#define ND 64
#define NTOK (NB * NT)

// ---- scratch ----
__device__ float g_x[NTOK * NC];
__device__ float g_h[NTOK * NC];
__device__ float g_qkv[NTOK * 3 * NC];
__device__ float g_y[NTOK * NC];
__device__ float g_fc[NTOK * 4 * NC];
__device__ float g_lmT[NC * NVP];

// =====================================================================
// helpers
// =====================================================================
__device__ __forceinline__ uint32_t smem_u32(const void* p) {
    uint32_t a;
    asm("{ .reg .u64 t; cvta.to.shared.u64 t, %1; cvt.u32.u64 %0, t; }"
        : "=r"(a) : "l"(p));
    return a;
}
__device__ __forceinline__ void cpa16(uint32_t dst, const void* src) {
    asm volatile("cp.async.cg.shared.global [%0], [%1], 16;"
                 :: "r"(dst), "l"(src));
}
__device__ __forceinline__ float gelu_f(float u) {
    return 0.5f * u * (1.0f + tanhf(0.7978845608028654f * (u + 0.044715f * u * u * u)));
}

// ---- packed f32x2 ----
__device__ __forceinline__ unsigned long long pack2(float x, float y) {
    unsigned long long r;
    asm("mov.b64 %0, {%1, %2};" : "=l"(r) : "f"(x), "f"(y));
    return r;
}
__device__ __forceinline__ void fma2(unsigned long long& c,
                                     unsigned long long a, unsigned long long b) {
    asm("fma.rn.f32x2 %0, %1, %2, %0;" : "+l"(c) : "l"(a), "l"(b));
}
__device__ __forceinline__ void mul2(unsigned long long& d,
                                     unsigned long long a, unsigned long long b) {
    asm("mul.rn.f32x2 %0, %1, %2;" : "=l"(d) : "l"(a), "l"(b));
}
__device__ __forceinline__ void unpack2(unsigned long long v, float& x, float& y) {
    asm("mov.b64 {%0, %1}, %2;" : "=f"(x), "=f"(y) : "l"(v));
}

// =====================================================================
// lm_head transpose: [NV][NC] -> [NC][NVP]
// =====================================================================
__global__ void transpose_lm(const float* __restrict__ src, float* __restrict__ dst) {
    __shared__ float t[32][33];
    int v0 = blockIdx.x * 32, c0 = blockIdx.y * 32;
    int tx = threadIdx.x, ty = threadIdx.y;
    #pragma unroll
    for (int i = ty; i < 32; i += 8)
        t[i][tx] = (v0 + i < NV) ? src[(size_t)(v0 + i) * NC + c0 + tx] : 0.f;
    __syncthreads();
    #pragma unroll
    for (int i = ty; i < 32; i += 8)
        dst[(size_t)(c0 + i) * NVP + v0 + tx] = t[tx][i];
}

// =====================================================================
// embedding
// =====================================================================
__global__ void embed_kernel(const int* __restrict__ idx,
                             const float* __restrict__ wte,
                             const float* __restrict__ wpe,
                             float* __restrict__ x) {
    int row = blockIdx.x;
    int t = row % NT;
    int tok = idx[row];
    const float* we = wte + (size_t)tok * NC;
    const float* wp = wpe + (size_t)t * NC;
    float* out = x + (size_t)row * NC;
    for (int c = threadIdx.x; c < NC; c += blockDim.x)
        out[c] = we[c] + wp[c];
}

// =====================================================================
// layernorm
// =====================================================================
__global__ void ln_kernel(const float* __restrict__ x,
                          const float* __restrict__ w,
                          const float* __restrict__ b,
                          float* __restrict__ out) {
    int row = blockIdx.x;
    const float* xr = x + (size_t)row * NC;
    __shared__ float red[32];
    int tid = threadIdx.x;
    int nwarp = blockDim.x >> 5;

    float s = 0.f;
    for (int c = tid; c < NC; c += blockDim.x) s += xr[c];
    #pragma unroll
    for (int o = 16; o; o >>= 1) s += __shfl_xor_sync(0xffffffffu, s, o);
    if ((tid & 31) == 0) red[tid >> 5] = s;
    __syncthreads();
    if (tid < 32) {
        float v = (tid < nwarp) ? red[tid] : 0.f;
        #pragma unroll
        for (int o = 16; o; o >>= 1) v += __shfl_xor_sync(0xffffffffu, v, o);
        if (tid == 0) red[0] = v;
    }
    __syncthreads();
    float mu = red[0] * (1.0f / NC);
    __syncthreads();

    float s2 = 0.f;
    for (int c = tid; c < NC; c += blockDim.x) {
        float d = xr[c] - mu;
        s2 += d * d;
    }
    #pragma unroll
    for (int o = 16; o; o >>= 1) s2 += __shfl_xor_sync(0xffffffffu, s2, o);
    if ((tid & 31) == 0) red[tid >> 5] = s2;
    __syncthreads();
    if (tid < 32) {
        float v = (tid < nwarp) ? red[tid] : 0.f;
        #pragma unroll
        for (int o = 16; o; o >>= 1) v += __shfl_xor_sync(0xffffffffu, v, o);
        if (tid == 0) red[0] = v;
    }
    __syncthreads();
    float var = red[0] * (1.0f / NC);
    float rstd = rsqrtf(var + 1e-5f);
    float* outr = out + (size_t)row * NC;
    for (int c = tid; c < NC; c += blockDim.x)
        outr[c] = (xr[c] - mu) * rstd * w[c] + b[c];
}

// =====================================================================
// fp32 SGEMM (NN), FFMA2; B pairs via ld.shared.v2.b64 on float smem;
// register double-buffered fragments to hide LDS + pack latency.
// =====================================================================
#define BM 128
#define BN 128
#define BKS 16

__global__ void __launch_bounds__(256, 2) sgemm_nn(
    const float* __restrict__ A, const float* __restrict__ W,
    const float* __restrict__ bias, const float* __restrict__ res,
    float* __restrict__ C, int M, int N, int ldb, int K, int act)
{
    __shared__ __align__(16) float As[2][BKS][BM];
    __shared__ __align__(16) float Bs[2][BKS][BN];

    int tid = threadIdx.x;
    int lane = tid & 31, warp = tid >> 5;
    int wm = (warp & 3) * 32, wn = (warp >> 2) * 64;
    int lm = lane & 3, ln = lane >> 2;
    int bm = blockIdx.x * BM, bn = blockIdx.y * BN;

    int arow = tid & 127, akq = (tid >> 7) * 8;
    float4 apre0, apre1;

    unsigned long long c2[8][4];
    #pragma unroll
    for (int i = 0; i < 8; i++)
        #pragma unroll
        for (int j = 0; j < 4; j++) c2[i][j] = 0ULL;

    const int S = K / BKS;

    {
        const float* ap = A + (size_t)(bm + arow) * K + akq;
        apre0 = *(const float4*)(ap);
        apre1 = *(const float4*)(ap + 4);
        #pragma unroll
        for (int i = 0; i < 2; i++) {
            int id = tid + i * 256;
            int k = id >> 5, n16 = (id & 31) * 4;
            cpa16(smem_u32(&Bs[0][k][n16]), W + (size_t)k * ldb + bn + n16);
        }
        asm volatile("cp.async.commit_group;");
        #pragma unroll
        for (int i = 0; i < 4; i++) As[0][akq + i][arow] = ((float*)&apre0)[i];
        #pragma unroll
        for (int i = 0; i < 4; i++) As[0][akq + 4 + i][arow] = ((float*)&apre1)[i];
        asm volatile("cp.async.wait_group 0;");
        __syncthreads();
    }

    for (int s = 0; s < S; s++) {
        int cur = s & 1, nxt = cur ^ 1;
        bool more = (s + 1 < S);
        if (more) {
            const float* ap = A + (size_t)(bm + arow) * K + (s + 1) * BKS + akq;
            apre0 = *(const float4*)(ap);
            apre1 = *(const float4*)(ap + 4);
            #pragma unroll
            for (int i = 0; i < 2; i++) {
                int id = tid + i * 256;
                int k = id >> 5, n16 = (id & 31) * 4;
                cpa16(smem_u32(&Bs[nxt][k][n16]),
                      W + (size_t)((s + 1) * BKS + k) * ldb + bn + n16);
            }
            asm volatile("cp.async.commit_group;");
        }

        // ---- register-pipelined k loop ----
        float af[2][8];
        ulonglong2 bA[2], bB[2];
        // fragment k = 0
        *(float4*)&af[0][0] = *(const float4*)&As[cur][0][wm + lm * 4];
        *(float4*)&af[0][4] = *(const float4*)&As[cur][0][wm + lm * 4 + 16];
        bA[0] = *(const ulonglong2*)&Bs[cur][0][wn + ln * 4];
        bB[0] = *(const ulonglong2*)&Bs[cur][0][wn + ln * 4 + 32];

        #pragma unroll
        for (int k = 0; k < BKS; k++) {
            int cb = k & 1, nb = cb ^ 1;
            if (k + 1 < BKS) {
                *(float4*)&af[nb][0] = *(const float4*)&As[cur][k + 1][wm + lm * 4];
                *(float4*)&af[nb][4] = *(const float4*)&As[cur][k + 1][wm + lm * 4 + 16];
                bA[nb] = *(const ulonglong2*)&Bs[cur][k + 1][wn + ln * 4];
                bB[nb] = *(const ulonglong2*)&Bs[cur][k + 1][wn + ln * 4 + 32];
            }
            #pragma unroll
            for (int i = 0; i < 8; i++) {
                unsigned long long a2 = pack2(af[cb][i], af[cb][i]);
                fma2(c2[i][0], a2, bA[cb].x);
                fma2(c2[i][1], a2, bA[cb].y);
                fma2(c2[i][2], a2, bB[cb].x);
                fma2(c2[i][3], a2, bB[cb].y);
            }
        }

        if (more) {
            #pragma unroll
            for (int i = 0; i < 4; i++) As[nxt][akq + i][arow] = ((float*)&apre0)[i];
            #pragma unroll
            for (int i = 0; i < 4; i++) As[nxt][akq + 4 + i][arow] = ((float*)&apre1)[i];
            asm volatile("cp.async.wait_group 0;");
        }
        __syncthreads();
    }

    // ---- epilogue ----
    bool vec_ok = ((N & 3) == 0);
    #pragma unroll
    for (int i = 0; i < 8; i++) {
        int m = bm + wm + (i >> 2) * 16 + lm * 4 + (i & 3);
        #pragma unroll
        for (int jq = 0; jq < 2; jq++) {
            int n0 = bn + wn + jq * 32 + ln * 4;
            float cv[4];
            unpack2(c2[i][jq * 2 + 0], cv[0], cv[1]);
            unpack2(c2[i][jq * 2 + 1], cv[2], cv[3]);
            float4 v;
            float* vp = (float*)&v;
            #pragma unroll
            for (int j = 0; j < 4; j++) {
                float u = cv[j];
                int col = n0 + j;
                if (bias) u += bias[col];
                if (act) u = gelu_f(u);
                if (res && col < N) u += res[(size_t)m * N + col];
                vp[j] = u;
            }
            if (vec_ok && n0 + 3 < N) {
                *(float4*)&C[(size_t)m * N + n0] = v;
            } else {
                #pragma unroll
                for (int j = 0; j < 4; j++)
                    if (n0 + j < N) C[(size_t)m * N + n0 + j] = vp[j];
            }
        }
    }
}

// =====================================================================
// FLASH ATTENTION (fp32, packed FFMA2) — R15 version (measured good)
// =====================================================================
#define FBQ 64
#define FPITCH 68
#define FSMEM_BYTES (4 * 64 * FPITCH * 4 + 3 * 64 * 4)

__global__ void __launch_bounds__(256) flash_attn(
    const float* __restrict__ qkv, float* __restrict__ y)
{
    extern __shared__ float fs[];
    float* Qt = fs;
    float* Kt = Qt + 64 * FPITCH;
    float* Vs = Kt + 64 * FPITCH;
    float* Ss = Vs + 64 * FPITCH;
    float* sm_m = Ss + 64 * FPITCH;
    float* sm_l = sm_m + 64;
    float* sm_a = sm_l + 64;

    int qt = blockIdx.x, h = blockIdx.y, b = blockIdx.z;
    int tid = threadIdx.x, lane = tid & 31, warp = tid >> 5;
    int q0 = qt * FBQ;
    const size_t rs = 3 * NC;
    const float* qbase = qkv + ((size_t)b * NT) * rs + h * ND;
    const float* kbase = qkv + ((size_t)b * NT) * rs + NC + h * ND;
    const float* vbase = qkv + ((size_t)b * NT) * rs + 2 * NC + h * ND;

    unsigned long long O2[8];
    #pragma unroll
    for (int i = 0; i < 8; i++) O2[i] = 0ULL;
    if (tid < 64) { sm_m[tid] = -1e30f; sm_l[tid] = 0.f; }

    #pragma unroll
    for (int i = 0; i < 4; i++) {
        int idx = tid + i * 256;
        int q = idx & 63, c4 = (idx >> 6) * 4;
        float4 v = *(const float4*)(qbase + (size_t)(q0 + q) * rs + c4);
        Qt[(c4 + 0) * FPITCH + q] = v.x;
        Qt[(c4 + 1) * FPITCH + q] = v.y;
        Qt[(c4 + 2) * FPITCH + q] = v.z;
        Qt[(c4 + 3) * FPITCH + q] = v.w;
    }
    __syncthreads();

    int tq = (tid & 15) * 4, tk = (tid >> 4) * 4;
    int pvq = warp * 8 + (lane & 7), dg = lane >> 3;

    for (int kt = 0; kt <= qt; kt++) {
        int kb = kt * FBQ;

        #pragma unroll
        for (int i = 0; i < 4; i++) {
            int idx = tid + i * 256;
            int k = idx & 63, c4 = (idx >> 6) * 4;
            float4 v = *(const float4*)(kbase + (size_t)(kb + k) * rs + c4);
            Kt[(c4 + 0) * FPITCH + k] = v.x;
            Kt[(c4 + 1) * FPITCH + k] = v.y;
            Kt[(c4 + 2) * FPITCH + k] = v.z;
            Kt[(c4 + 3) * FPITCH + k] = v.w;
            float4 w = *(const float4*)(vbase + (size_t)(kb + k) * rs + c4);
            *(float4*)&Vs[k * FPITCH + c4] = w;
        }
        __syncthreads();

        unsigned long long s2[4][2];
        #pragma unroll
        for (int i = 0; i < 4; i++) { s2[i][0] = 0ULL; s2[i][1] = 0ULL; }
        #pragma unroll 8
        for (int d = 0; d < 64; d++) {
            float4 a4 = *(const float4*)&Qt[d * FPITCH + tq];
            float4 b4 = *(const float4*)&Kt[d * FPITCH + tk];
            const float* aa = (const float*)&a4;
            unsigned long long bb0 = pack2(b4.x, b4.y);
            unsigned long long bb1 = pack2(b4.z, b4.w);
            #pragma unroll
            for (int i = 0; i < 4; i++) {
                unsigned long long a2 = pack2(aa[i], aa[i]);
                fma2(s2[i][0], a2, bb0);
                fma2(s2[i][1], a2, bb1);
            }
        }
        bool diag = (kt == qt);
        #pragma unroll
        for (int i = 0; i < 4; i++) {
            float sv[4];
            unpack2(s2[i][0], sv[0], sv[1]);
            unpack2(s2[i][1], sv[2], sv[3]);
            float4 v;
            float* vp = (float*)&v;
            #pragma unroll
            for (int j = 0; j < 4; j++) {
                float val = sv[j] * 0.125f;
                if (diag && (kb + tk + j) > (q0 + tq + i)) val = -1e30f;
                vp[j] = val;
            }
            *(float4*)&Ss[(tq + i) * FPITCH + tk] = v;
        }
        __syncthreads();

        for (int r = 0; r < 8; r++) {
            int q = warp * 8 + r;
            float s0 = Ss[q * FPITCH + lane];
            float s1 = Ss[q * FPITCH + lane + 32];
            float mx = fmaxf(s0, s1);
            #pragma unroll
            for (int o = 16; o; o >>= 1)
                mx = fmaxf(mx, __shfl_xor_sync(0xffffffffu, mx, o));
            float mo = sm_m[q];
            float mn = fmaxf(mo, mx);
            float p0 = __expf(s0 - mn), p1 = __expf(s1 - mn);
            float ps = p0 + p1;
            #pragma unroll
            for (int o = 16; o; o >>= 1)
                ps += __shfl_xor_sync(0xffffffffu, ps, o);
            Ss[q * FPITCH + lane] = p0;
            Ss[q * FPITCH + lane + 32] = p1;
            if (lane == 0) {
                float al = __expf(mo - mn);
                sm_a[q] = al;
                sm_l[q] = sm_l[q] * al + ps;
                sm_m[q] = mn;
            }
        }
        __syncthreads();

        {
            float al = sm_a[pvq];
            unsigned long long al2 = pack2(al, al);
            #pragma unroll
            for (int i = 0; i < 8; i++) mul2(O2[i], O2[i], al2);
        }
        #pragma unroll 4
        for (int k = 0; k < 64; k++) {
            float p = Ss[pvq * FPITCH + k];
            unsigned long long p2 = pack2(p, p);
            const float4* vr = (const float4*)&Vs[k * FPITCH + dg * 16];
            #pragma unroll
            for (int q4 = 0; q4 < 4; q4++) {
                float4 v = vr[q4];
                fma2(O2[q4 * 2 + 0], p2, pack2(v.x, v.y));
                fma2(O2[q4 * 2 + 1], p2, pack2(v.z, v.w));
            }
        }
        __syncthreads();
    }

    float inv = 1.0f / sm_l[pvq];
    float* yo = y + ((size_t)(b * NT + q0 + pvq)) * NC + h * ND + dg * 16;
    #pragma unroll
    for (int j = 0; j < 4; j++) {
        float x0, x1, x2, x3;
        unpack2(O2[j * 2 + 0], x0, x1);
        unpack2(O2[j * 2 + 1], x2, x3);
        float4 v = make_float4(x0 * inv, x1 * inv, x2 * inv, x3 * inv);
        *(float4*)(yo + j * 4) = v;
    }
}

// =====================================================================
// launch
// =====================================================================
extern "C" void kernel_launch(void* const* d_in, const int* in_sizes, int n_in,
                              void* d_out, int out_size) {
    const int*   idx    = (const int*)d_in[0];
    const float* wte    = (const float*)d_in[1];
    const float* wpe    = (const float*)d_in[2];
    const float* ln1_w  = (const float*)d_in[3];
    const float* ln1_b  = (const float*)d_in[4];
    const float* ln2_w  = (const float*)d_in[5];
    const float* ln2_b  = (const float*)d_in[6];
    const float* attn_w = (const float*)d_in[7];
    const float* attn_b = (const float*)d_in[8];
    const float* proj_w = (const float*)d_in[9];
    const float* proj_b = (const float*)d_in[10];
    const float* fc_w   = (const float*)d_in[11];
    const float* fc_b   = (const float*)d_in[12];
    const float* fcp_w  = (const float*)d_in[13];
    const float* fcp_b  = (const float*)d_in[14];
    const float* lnf_w  = (const float*)d_in[15];
    const float* lnf_b  = (const float*)d_in[16];
    const float* lmh    = (const float*)d_in[17];
    float* out = (float*)d_out;

    float *x, *h, *qkv, *y, *fc, *lmT;
    cudaGetSymbolAddress((void**)&x, g_x);
    cudaGetSymbolAddress((void**)&h, g_h);
    cudaGetSymbolAddress((void**)&qkv, g_qkv);
    cudaGetSymbolAddress((void**)&y, g_y);
    cudaGetSymbolAddress((void**)&fc, g_fc);
    cudaGetSymbolAddress((void**)&lmT, g_lmT);

    cudaFuncSetAttribute(flash_attn, cudaFuncAttributeMaxDynamicSharedMemorySize,
                         FSMEM_BYTES);

    transpose_lm<<<dim3(NVP / 32, NC / 32), dim3(32, 8)>>>(lmh, lmT);
    embed_kernel<<<NTOK, 256>>>(idx, wte, wpe, x);

    for (int l = 0; l < NL; l++) {
        ln_kernel<<<NTOK, 256>>>(x, ln1_w + l * NC, ln1_b + l * NC, h);
        sgemm_nn<<<dim3(NTOK / BM, (3 * NC) / BN), 256>>>(
            h, attn_w + (size_t)l * NC * 3 * NC,
            attn_b + (size_t)l * 3 * NC, nullptr,
            qkv, NTOK, 3 * NC, 3 * NC, NC, 0);
        {
            dim3 grid(NT / FBQ, NH, NB);
            flash_attn<<<grid, 256, FSMEM_BYTES>>>(qkv, y);
        }
        sgemm_nn<<<dim3(NTOK / BM, NC / BN), 256>>>(
            y, proj_w + (size_t)l * NC * NC,
            proj_b + (size_t)l * NC, x,
            x, NTOK, NC, NC, NC, 0);
        ln_kernel<<<NTOK, 256>>>(x, ln2_w + l * NC, ln2_b + l * NC, h);
        sgemm_nn<<<dim3(NTOK / BM, (4 * NC) / BN), 256>>>(
            h, fc_w + (size_t)l * NC * 4 * NC,
            fc_b + (size_t)l * 4 * NC, nullptr,
            fc, NTOK, 4 * NC, 4 * NC, NC, 1);
        sgemm_nn<<<dim3(NTOK / BM, NC / BN), 256>>>(
            fc, fcp_w + (size_t)l * 4 * NC * NC,
            fcp_b + (size_t)l * NC, x,
            x, NTOK, NC, NC, 4 * NC, 0);
    }

    ln_kernel<<<NTOK, 256>>>(x, lnf_w, lnf_b, h);

    sgemm_nn<<<dim3(NTOK / BM, NVP / BN), 256>>>(
        h, lmT, nullptr, nullptr, out, NTOK, NV, NVP, NC, 0);
}